// round 1
// baseline (speedup 1.0000x reference)
#include <cuda_runtime.h>
#include <cstdint>

#define S_LEN   2048
#define D_MODEL 1024
#define NH      16
#define DKH     64
#define BATCH   2
#define M_TOTAL (BATCH * S_LEN)   // 4096

// Scratch: Q/K/V in [B,H,S,dk] layout, attention output in [B*S, D] layout.
__device__ float g_q [BATCH * NH * S_LEN * DKH];
__device__ float g_k [BATCH * NH * S_LEN * DKH];
__device__ float g_v [BATCH * NH * S_LEN * DKH];
__device__ float g_ao[M_TOTAL * D_MODEL];

__device__ __forceinline__ float f2tf32(float x) {
    uint32_t u;
    asm("cvt.rna.tf32.f32 %0, %1;" : "=r"(u) : "f"(x));
    return __uint_as_float(u);
}

__device__ __forceinline__ void mma_tf32(float c[4], const uint32_t a[4], const uint32_t b[2]) {
    asm volatile(
        "mma.sync.aligned.m16n8k8.row.col.f32.tf32.tf32.f32 "
        "{%0,%1,%2,%3}, {%4,%5,%6,%7}, {%8,%9}, {%0,%1,%2,%3};"
        : "+f"(c[0]), "+f"(c[1]), "+f"(c[2]), "+f"(c[3])
        : "r"(a[0]), "r"(a[1]), "r"(a[2]), "r"(a[3]),
          "r"(b[0]), "r"(b[1]));
}

// ============================================================================
// TF32 GEMM: out[M,N] = A[M,K] @ W[K,N] + bias.  M=4096, N=K=1024.
// Block tile 128x128, K-chunk 32, 8 warps (2x4), warp tile 64x32.
// LAYOUT 0: row-major [M, N] output.
// LAYOUT 1: scatter to [B, H, S, dk] (q/k/v scratch).
// ============================================================================
template <int LAYOUT>
__global__ __launch_bounds__(256)
void gemm_tf32_kernel(const float* __restrict__ A, const float* __restrict__ W,
                      const float* __restrict__ bias, float* __restrict__ out) {
    __shared__ float As[128][36];   // stride 36: conflict-free A fragments
    __shared__ float Bs[32][136];   // stride 136: conflict-free B fragments

    const int t    = threadIdx.x;
    const int lane = t & 31;
    const int warp = t >> 5;
    const int gid  = lane >> 2;     // group id 0..7
    const int tig  = lane & 3;      // thread in group 0..3
    const int wm   = (warp >> 2) * 64;  // warp row base within block
    const int wn   = (warp & 3) * 32;   // warp col base within block
    const int m0   = blockIdx.y * 128;
    const int n0   = blockIdx.x * 128;

    float acc[4][4][4];
#pragma unroll
    for (int i = 0; i < 4; i++)
#pragma unroll
        for (int j = 0; j < 4; j++)
#pragma unroll
            for (int k = 0; k < 4; k++) acc[i][j][k] = 0.f;

    // global->reg prefetch indices
    const int ar = t >> 3;          // A row (0..31), +32 per pass
    const int ac = (t & 7) * 4;     // A col (float4)
    const int br = t >> 5;          // B row (0..7), +8 per pass
    const int bc = (t & 31) * 4;    // B col (float4)

    float4 pa[4], pb[4];
#pragma unroll
    for (int p = 0; p < 4; p++)
        pa[p] = *(const float4*)&A[(size_t)(m0 + ar + 32 * p) * D_MODEL + ac];
#pragma unroll
    for (int p = 0; p < 4; p++)
        pb[p] = *(const float4*)&W[(size_t)(br + 8 * p) * D_MODEL + n0 + bc];

    for (int kb = 0; kb < D_MODEL; kb += 32) {
#pragma unroll
        for (int p = 0; p < 4; p++) {
            As[ar + 32 * p][ac + 0] = f2tf32(pa[p].x);
            As[ar + 32 * p][ac + 1] = f2tf32(pa[p].y);
            As[ar + 32 * p][ac + 2] = f2tf32(pa[p].z);
            As[ar + 32 * p][ac + 3] = f2tf32(pa[p].w);
            Bs[br + 8 * p][bc + 0] = f2tf32(pb[p].x);
            Bs[br + 8 * p][bc + 1] = f2tf32(pb[p].y);
            Bs[br + 8 * p][bc + 2] = f2tf32(pb[p].z);
            Bs[br + 8 * p][bc + 3] = f2tf32(pb[p].w);
        }
        __syncthreads();

        if (kb + 32 < D_MODEL) {
#pragma unroll
            for (int p = 0; p < 4; p++)
                pa[p] = *(const float4*)&A[(size_t)(m0 + ar + 32 * p) * D_MODEL + kb + 32 + ac];
#pragma unroll
            for (int p = 0; p < 4; p++)
                pb[p] = *(const float4*)&W[(size_t)(kb + 32 + br + 8 * p) * D_MODEL + n0 + bc];
        }

#pragma unroll
        for (int kk = 0; kk < 32; kk += 8) {
            uint32_t a[4][4], b[4][2];
#pragma unroll
            for (int mt = 0; mt < 4; mt++) {
                int r = wm + mt * 16 + gid;
                a[mt][0] = __float_as_uint(As[r][kk + tig]);
                a[mt][1] = __float_as_uint(As[r + 8][kk + tig]);
                a[mt][2] = __float_as_uint(As[r][kk + 4 + tig]);
                a[mt][3] = __float_as_uint(As[r + 8][kk + 4 + tig]);
            }
#pragma unroll
            for (int nt = 0; nt < 4; nt++) {
                int cc = wn + nt * 8 + gid;
                b[nt][0] = __float_as_uint(Bs[kk + tig][cc]);
                b[nt][1] = __float_as_uint(Bs[kk + 4 + tig][cc]);
            }
#pragma unroll
            for (int mt = 0; mt < 4; mt++)
#pragma unroll
                for (int nt = 0; nt < 4; nt++)
                    mma_tf32(acc[mt][nt], a[mt], b[nt]);
        }
        __syncthreads();
    }

    // epilogue: + bias, scatter per LAYOUT
#pragma unroll
    for (int mt = 0; mt < 4; mt++)
#pragma unroll
        for (int nt = 0; nt < 4; nt++) {
            int c0 = n0 + wn + nt * 8 + tig * 2;
            float b0 = bias[c0], b1 = bias[c0 + 1];
#pragma unroll
            for (int h2 = 0; h2 < 2; h2++) {
                int r = m0 + wm + mt * 16 + gid + 8 * h2;
                float v0 = acc[mt][nt][2 * h2 + 0] + b0;
                float v1 = acc[mt][nt][2 * h2 + 1] + b1;
                if (LAYOUT == 0) {
                    *(float2*)&out[(size_t)r * D_MODEL + c0] = make_float2(v0, v1);
                } else {
                    int bb = r >> 11, ss = r & 2047;
                    int hh = c0 >> 6, dd = c0 & 63;
                    size_t idx = ((size_t)((bb * NH + hh) * S_LEN) + ss) * DKH + dd;
                    *(float2*)&out[idx] = make_float2(v0, v1);
                }
            }
        }
}

// ============================================================================
// Flash attention: per (b,h), Q-tile 128 rows x dk=64, stream 16 KV tiles of
// 128, online softmax, TF32 mma for both QK^T and PV. 8 warps (16 rows each).
// ============================================================================
#define QS_STR 68
#define KS_STR 68
#define VS_STR 72
#define PS_STR 132
#define SM_K   (128 * QS_STR)
#define SM_V   (SM_K + 128 * KS_STR)
#define SM_P   (SM_V + 128 * VS_STR)
#define SM_TOT (SM_P + 128 * PS_STR)      // floats; *4 = 174080 bytes

__global__ __launch_bounds__(256, 1)
void attn_kernel(const float* __restrict__ Q, const float* __restrict__ K,
                 const float* __restrict__ V, float* __restrict__ AO) {
    extern __shared__ float sm[];
    float* Qs = sm;
    float* Ks = sm + SM_K;
    float* Vs = sm + SM_V;
    float* Ps = sm + SM_P;

    const int t    = threadIdx.x;
    const int lane = t & 31;
    const int warp = t >> 5;
    const int gid  = lane >> 2;
    const int tig  = lane & 3;
    const int qt   = blockIdx.x;   // 0..15
    const int bh   = blockIdx.y;   // 0..31
    const int rA   = warp * 16 + gid;   // this lane's base row within tile

    const float* qg = Q + ((size_t)bh * S_LEN + qt * 128) * DKH;
    const float* kg = K + (size_t)bh * S_LEN * DKH;
    const float* vg = V + (size_t)bh * S_LEN * DKH;

    // Load Q tile (128 x 64), tf32-rounded
#pragma unroll
    for (int p = 0; p < 8; p++) {
        int idx = t + p * 256;
        int r = idx >> 4, c = (idx & 15) * 4;
        float4 v = *(const float4*)&qg[r * DKH + c];
        Qs[r * QS_STR + c + 0] = f2tf32(v.x);
        Qs[r * QS_STR + c + 1] = f2tf32(v.y);
        Qs[r * QS_STR + c + 2] = f2tf32(v.z);
        Qs[r * QS_STR + c + 3] = f2tf32(v.w);
    }

    float o[8][4];
#pragma unroll
    for (int i = 0; i < 8; i++)
#pragma unroll
        for (int j = 0; j < 4; j++) o[i][j] = 0.f;
    float mrow0 = -1e30f, mrow1 = -1e30f, lrow0 = 0.f, lrow1 = 0.f;

    for (int kt = 0; kt < 16; kt++) {
        __syncthreads();   // previous iteration's Ks/Vs reads done
        const float* kgt = kg + kt * 128 * DKH;
        const float* vgt = vg + kt * 128 * DKH;
#pragma unroll
        for (int p = 0; p < 8; p++) {
            int idx = t + p * 256;
            int r = idx >> 4, c = (idx & 15) * 4;
            float4 kv = *(const float4*)&kgt[r * DKH + c];
            Ks[r * KS_STR + c + 0] = f2tf32(kv.x);
            Ks[r * KS_STR + c + 1] = f2tf32(kv.y);
            Ks[r * KS_STR + c + 2] = f2tf32(kv.z);
            Ks[r * KS_STR + c + 3] = f2tf32(kv.w);
            float4 vv = *(const float4*)&vgt[r * DKH + c];
            Vs[r * VS_STR + c + 0] = f2tf32(vv.x);
            Vs[r * VS_STR + c + 1] = f2tf32(vv.y);
            Vs[r * VS_STR + c + 2] = f2tf32(vv.z);
            Vs[r * VS_STR + c + 3] = f2tf32(vv.w);
        }
        __syncthreads();

        // S = Q @ K^T  (warp: 16 rows x 128 cols)
        float s[16][4];
#pragma unroll
        for (int i = 0; i < 16; i++)
#pragma unroll
            for (int j = 0; j < 4; j++) s[i][j] = 0.f;

#pragma unroll
        for (int kk = 0; kk < 64; kk += 8) {
            uint32_t a[4];
            a[0] = __float_as_uint(Qs[rA * QS_STR + kk + tig]);
            a[1] = __float_as_uint(Qs[(rA + 8) * QS_STR + kk + tig]);
            a[2] = __float_as_uint(Qs[rA * QS_STR + kk + 4 + tig]);
            a[3] = __float_as_uint(Qs[(rA + 8) * QS_STR + kk + 4 + tig]);
#pragma unroll
            for (int nt = 0; nt < 16; nt++) {
                uint32_t b[2];
                b[0] = __float_as_uint(Ks[(nt * 8 + gid) * KS_STR + kk + tig]);
                b[1] = __float_as_uint(Ks[(nt * 8 + gid) * KS_STR + kk + 4 + tig]);
                mma_tf32(s[nt], a, b);
            }
        }

        // online softmax (rows rA and rA+8; reduce across tig via shfl)
        float mx0 = -1e30f, mx1 = -1e30f;
#pragma unroll
        for (int nt = 0; nt < 16; nt++) {
            s[nt][0] *= 0.125f; s[nt][1] *= 0.125f;
            s[nt][2] *= 0.125f; s[nt][3] *= 0.125f;
            mx0 = fmaxf(mx0, fmaxf(s[nt][0], s[nt][1]));
            mx1 = fmaxf(mx1, fmaxf(s[nt][2], s[nt][3]));
        }
        mx0 = fmaxf(mx0, __shfl_xor_sync(0xffffffffu, mx0, 1));
        mx0 = fmaxf(mx0, __shfl_xor_sync(0xffffffffu, mx0, 2));
        mx1 = fmaxf(mx1, __shfl_xor_sync(0xffffffffu, mx1, 1));
        mx1 = fmaxf(mx1, __shfl_xor_sync(0xffffffffu, mx1, 2));

        float nm0 = fmaxf(mrow0, mx0), nm1 = fmaxf(mrow1, mx1);
        float al0 = __expf(mrow0 - nm0), al1 = __expf(mrow1 - nm1);
        mrow0 = nm0; mrow1 = nm1;

        float sum0 = 0.f, sum1 = 0.f;
#pragma unroll
        for (int nt = 0; nt < 16; nt++) {
            float p0 = __expf(s[nt][0] - nm0), p1 = __expf(s[nt][1] - nm0);
            float p2 = __expf(s[nt][2] - nm1), p3 = __expf(s[nt][3] - nm1);
            sum0 += p0 + p1; sum1 += p2 + p3;
            int cc = nt * 8 + tig * 2;
            *(float2*)&Ps[rA * PS_STR + cc]       = make_float2(f2tf32(p0), f2tf32(p1));
            *(float2*)&Ps[(rA + 8) * PS_STR + cc] = make_float2(f2tf32(p2), f2tf32(p3));
        }
        sum0 += __shfl_xor_sync(0xffffffffu, sum0, 1);
        sum0 += __shfl_xor_sync(0xffffffffu, sum0, 2);
        sum1 += __shfl_xor_sync(0xffffffffu, sum1, 1);
        sum1 += __shfl_xor_sync(0xffffffffu, sum1, 2);
        lrow0 = lrow0 * al0 + sum0;
        lrow1 = lrow1 * al1 + sum1;
#pragma unroll
        for (int nt = 0; nt < 8; nt++) {
            o[nt][0] *= al0; o[nt][1] *= al0;
            o[nt][2] *= al1; o[nt][3] *= al1;
        }
        __syncwarp();   // Ps rows are warp-private; order write->read

        // O += P @ V  (warp: 16 rows x 64 cols, k over 128)
#pragma unroll
        for (int kk = 0; kk < 128; kk += 8) {
            uint32_t a[4];
            a[0] = __float_as_uint(Ps[rA * PS_STR + kk + tig]);
            a[1] = __float_as_uint(Ps[(rA + 8) * PS_STR + kk + tig]);
            a[2] = __float_as_uint(Ps[rA * PS_STR + kk + 4 + tig]);
            a[3] = __float_as_uint(Ps[(rA + 8) * PS_STR + kk + 4 + tig]);
#pragma unroll
            for (int nt = 0; nt < 8; nt++) {
                uint32_t b[2];
                b[0] = __float_as_uint(Vs[(kk + tig) * VS_STR + nt * 8 + gid]);
                b[1] = __float_as_uint(Vs[(kk + 4 + tig) * VS_STR + nt * 8 + gid]);
                mma_tf32(o[nt], a, b);
            }
        }
    }

    // epilogue: normalize, scatter to [B*S, D] with head offset
    float il0 = 1.f / lrow0, il1 = 1.f / lrow1;
    int bb = bh >> 4, hh = bh & 15;
    int q0 = qt * 128 + rA;
    size_t base0 = ((size_t)(bb * S_LEN + q0)) * D_MODEL + hh * DKH;
    size_t base1 = base0 + (size_t)8 * D_MODEL;
#pragma unroll
    for (int nt = 0; nt < 8; nt++) {
        int dd = nt * 8 + tig * 2;
        *(float2*)&AO[base0 + dd] = make_float2(o[nt][0] * il0, o[nt][1] * il0);
        *(float2*)&AO[base1 + dd] = make_float2(o[nt][2] * il1, o[nt][3] * il1);
    }
}

// ============================================================================
extern "C" void kernel_launch(void* const* d_in, const int* in_sizes, int n_in,
                              void* d_out, int out_size) {
    (void)in_sizes; (void)n_in; (void)out_size;
    const float* x  = (const float*)d_in[0];
    const float* Wq = (const float*)d_in[1];
    const float* bq = (const float*)d_in[2];
    const float* Wk = (const float*)d_in[3];
    const float* bk = (const float*)d_in[4];
    const float* Wv = (const float*)d_in[5];
    const float* bv = (const float*)d_in[6];
    const float* Wo = (const float*)d_in[7];
    const float* bo = (const float*)d_in[8];
    float* out = (float*)d_out;

    float *pq, *pk, *pv, *pao;
    cudaGetSymbolAddress((void**)&pq,  g_q);
    cudaGetSymbolAddress((void**)&pk,  g_k);
    cudaGetSymbolAddress((void**)&pv,  g_v);
    cudaGetSymbolAddress((void**)&pao, g_ao);

    cudaFuncSetAttribute(attn_kernel,
                         cudaFuncAttributeMaxDynamicSharedMemorySize,
                         SM_TOT * (int)sizeof(float));

    dim3 gg(D_MODEL / 128, M_TOTAL / 128);   // (8, 32)
    gemm_tf32_kernel<1><<<gg, 256>>>(x, Wq, bq, pq);
    gemm_tf32_kernel<1><<<gg, 256>>>(x, Wk, bk, pk);
    gemm_tf32_kernel<1><<<gg, 256>>>(x, Wv, bv, pv);
    attn_kernel<<<dim3(16, 32), 256, SM_TOT * sizeof(float)>>>(pq, pk, pv, pao);
    gemm_tf32_kernel<0><<<gg, 256>>>(pao, Wo, bo, out);
}

// round 2
// speedup vs baseline: 1.0581x; 1.0581x over previous
#include <cuda_runtime.h>
#include <cstdint>

#define S_LEN   2048
#define D_MODEL 1024
#define NH      16
#define DKH     64
#define BATCH   2
#define M_TOTAL (BATCH * S_LEN)   // 4096

// Scratch: Q/K/V in [B,H,S,dk] layout, attention output in [B*S, D] layout.
__device__ float g_q [BATCH * NH * S_LEN * DKH];
__device__ float g_k [BATCH * NH * S_LEN * DKH];
__device__ float g_v [BATCH * NH * S_LEN * DKH];
__device__ float g_ao[M_TOTAL * D_MODEL];

__device__ __forceinline__ float f2tf32(float x) {
    uint32_t u;
    asm("cvt.rna.tf32.f32 %0, %1;" : "=r"(u) : "f"(x));
    return __uint_as_float(u);
}

__device__ __forceinline__ void mma_tf32(float c[4], const uint32_t a[4], const uint32_t b[2]) {
    asm volatile(
        "mma.sync.aligned.m16n8k8.row.col.f32.tf32.tf32.f32 "
        "{%0,%1,%2,%3}, {%4,%5,%6,%7}, {%8,%9}, {%0,%1,%2,%3};"
        : "+f"(c[0]), "+f"(c[1]), "+f"(c[2]), "+f"(c[3])
        : "r"(a[0]), "r"(a[1]), "r"(a[2]), "r"(a[3]),
          "r"(b[0]), "r"(b[1]));
}

// ============================================================================
// TF32 GEMM core: out[M,N] = A[M,K] @ W[K,N] + bias.  M=4096, N=K=1024.
// Block tile 128x128, K-chunk 32, 8 warps (2x4), warp tile 64x32.
// LAYOUT 0: row-major [M, N] output.
// LAYOUT 1: scatter to [B, H, S, dk] (q/k/v scratch).
// ============================================================================
template <int LAYOUT>
__device__ __forceinline__
void gemm_tf32_body(const float* __restrict__ A, const float* __restrict__ W,
                    const float* __restrict__ bias, float* __restrict__ out) {
    __shared__ float As[128][36];   // stride 36: conflict-free A fragments
    __shared__ float Bs[32][136];   // stride 136: conflict-free B fragments

    const int t    = threadIdx.x;
    const int lane = t & 31;
    const int warp = t >> 5;
    const int gid  = lane >> 2;     // group id 0..7
    const int tig  = lane & 3;      // thread in group 0..3
    const int wm   = (warp >> 2) * 64;  // warp row base within block
    const int wn   = (warp & 3) * 32;   // warp col base within block
    const int m0   = blockIdx.y * 128;
    const int n0   = blockIdx.x * 128;

    float acc[4][4][4];
#pragma unroll
    for (int i = 0; i < 4; i++)
#pragma unroll
        for (int j = 0; j < 4; j++)
#pragma unroll
            for (int k = 0; k < 4; k++) acc[i][j][k] = 0.f;

    // global->reg prefetch indices
    const int ar = t >> 3;          // A row (0..31), +32 per pass
    const int ac = (t & 7) * 4;     // A col (float4)
    const int br = t >> 5;          // B row (0..7), +8 per pass
    const int bc = (t & 31) * 4;    // B col (float4)

    float4 pa[4], pb[4];
#pragma unroll
    for (int p = 0; p < 4; p++)
        pa[p] = *(const float4*)&A[(size_t)(m0 + ar + 32 * p) * D_MODEL + ac];
#pragma unroll
    for (int p = 0; p < 4; p++)
        pb[p] = *(const float4*)&W[(size_t)(br + 8 * p) * D_MODEL + n0 + bc];

    for (int kb = 0; kb < D_MODEL; kb += 32) {
#pragma unroll
        for (int p = 0; p < 4; p++) {
            As[ar + 32 * p][ac + 0] = f2tf32(pa[p].x);
            As[ar + 32 * p][ac + 1] = f2tf32(pa[p].y);
            As[ar + 32 * p][ac + 2] = f2tf32(pa[p].z);
            As[ar + 32 * p][ac + 3] = f2tf32(pa[p].w);
            Bs[br + 8 * p][bc + 0] = f2tf32(pb[p].x);
            Bs[br + 8 * p][bc + 1] = f2tf32(pb[p].y);
            Bs[br + 8 * p][bc + 2] = f2tf32(pb[p].z);
            Bs[br + 8 * p][bc + 3] = f2tf32(pb[p].w);
        }
        __syncthreads();

        if (kb + 32 < D_MODEL) {
#pragma unroll
            for (int p = 0; p < 4; p++)
                pa[p] = *(const float4*)&A[(size_t)(m0 + ar + 32 * p) * D_MODEL + kb + 32 + ac];
#pragma unroll
            for (int p = 0; p < 4; p++)
                pb[p] = *(const float4*)&W[(size_t)(kb + 32 + br + 8 * p) * D_MODEL + n0 + bc];
        }

#pragma unroll
        for (int kk = 0; kk < 32; kk += 8) {
            uint32_t a[4][4], b[4][2];
#pragma unroll
            for (int mt = 0; mt < 4; mt++) {
                int r = wm + mt * 16 + gid;
                a[mt][0] = __float_as_uint(As[r][kk + tig]);
                a[mt][1] = __float_as_uint(As[r + 8][kk + tig]);
                a[mt][2] = __float_as_uint(As[r][kk + 4 + tig]);
                a[mt][3] = __float_as_uint(As[r + 8][kk + 4 + tig]);
            }
#pragma unroll
            for (int nt = 0; nt < 4; nt++) {
                int cc = wn + nt * 8 + gid;
                b[nt][0] = __float_as_uint(Bs[kk + tig][cc]);
                b[nt][1] = __float_as_uint(Bs[kk + 4 + tig][cc]);
            }
#pragma unroll
            for (int mt = 0; mt < 4; mt++)
#pragma unroll
                for (int nt = 0; nt < 4; nt++)
                    mma_tf32(acc[mt][nt], a[mt], b[nt]);
        }
        __syncthreads();
    }

    // epilogue: + bias, scatter per LAYOUT
#pragma unroll
    for (int mt = 0; mt < 4; mt++)
#pragma unroll
        for (int nt = 0; nt < 4; nt++) {
            int c0 = n0 + wn + nt * 8 + tig * 2;
            float b0 = bias[c0], b1 = bias[c0 + 1];
#pragma unroll
            for (int h2 = 0; h2 < 2; h2++) {
                int r = m0 + wm + mt * 16 + gid + 8 * h2;
                float v0 = acc[mt][nt][2 * h2 + 0] + b0;
                float v1 = acc[mt][nt][2 * h2 + 1] + b1;
                if (LAYOUT == 0) {
                    *(float2*)&out[(size_t)r * D_MODEL + c0] = make_float2(v0, v1);
                } else {
                    int bb = r >> 11, ss = r & 2047;
                    int hh = c0 >> 6, dd = c0 & 63;
                    size_t idx = ((size_t)((bb * NH + hh) * S_LEN) + ss) * DKH + dd;
                    *(float2*)&out[idx] = make_float2(v0, v1);
                }
            }
        }
}

// Fused QKV: one launch, blockIdx.z selects projection (kills 2 wave tails).
__global__ __launch_bounds__(256)
void gemm_qkv_kernel(const float* __restrict__ x,
                     const float* __restrict__ Wq, const float* __restrict__ bq,
                     const float* __restrict__ Wk, const float* __restrict__ bk,
                     const float* __restrict__ Wv, const float* __restrict__ bv,
                     float* __restrict__ oq, float* __restrict__ ok,
                     float* __restrict__ ov) {
    const float* W; const float* b; float* o;
    if (blockIdx.z == 0)      { W = Wq; b = bq; o = oq; }
    else if (blockIdx.z == 1) { W = Wk; b = bk; o = ok; }
    else                      { W = Wv; b = bv; o = ov; }
    gemm_tf32_body<1>(x, W, b, o);
}

__global__ __launch_bounds__(256)
void gemm_out_kernel(const float* __restrict__ A, const float* __restrict__ W,
                     const float* __restrict__ bias, float* __restrict__ out) {
    gemm_tf32_body<0>(A, W, bias, out);
}

// ============================================================================
// Flash attention: per (b,h), Q-tile 256 rows x dk=64, stream 32 KV tiles of
// 64, online softmax, TF32 mma. 16 warps (16 Q-rows each), 512 threads.
// Regs capped at 128/thread so 16 warps fit (4/SMSP -> latency hiding).
// ============================================================================
#define QT      256
#define KT      64
#define QS_STR  68
#define KS_STR  68
#define VS_STR  72
#define PS_STR  68
#define SM_K    (QT * QS_STR)
#define SM_V    (SM_K + KT * KS_STR)
#define SM_P    (SM_V + KT * VS_STR)
#define SM_TOT  (SM_P + QT * PS_STR)      // floats; *4 = 175104 bytes

__global__ __launch_bounds__(512, 1)
void attn_kernel(const float* __restrict__ Q, const float* __restrict__ K,
                 const float* __restrict__ V, float* __restrict__ AO) {
    extern __shared__ float sm[];
    float* Qs = sm;
    float* Ks = sm + SM_K;
    float* Vs = sm + SM_V;
    float* Ps = sm + SM_P;

    const int t    = threadIdx.x;
    const int lane = t & 31;
    const int warp = t >> 5;            // 0..15
    const int gid  = lane >> 2;
    const int tig  = lane & 3;
    const int qt   = blockIdx.x;        // 0..7
    const int bh   = blockIdx.y;        // 0..31
    const int rA   = warp * 16 + gid;   // base row within 256-row tile

    const float* qg = Q + ((size_t)bh * S_LEN + qt * QT) * DKH;
    const float* kg = K + (size_t)bh * S_LEN * DKH;
    const float* vg = V + (size_t)bh * S_LEN * DKH;

    // Load Q tile (256 x 64), tf32-rounded. 512 thr * 8 passes * 4 = 16384.
#pragma unroll
    for (int p = 0; p < 8; p++) {
        int idx = t + p * 512;
        int r = idx >> 4, c = (idx & 15) * 4;
        float4 v = *(const float4*)&qg[r * DKH + c];
        Qs[r * QS_STR + c + 0] = f2tf32(v.x);
        Qs[r * QS_STR + c + 1] = f2tf32(v.y);
        Qs[r * QS_STR + c + 2] = f2tf32(v.z);
        Qs[r * QS_STR + c + 3] = f2tf32(v.w);
    }

    float o[8][4];
#pragma unroll
    for (int i = 0; i < 8; i++)
#pragma unroll
        for (int j = 0; j < 4; j++) o[i][j] = 0.f;
    float mrow0 = -1e30f, mrow1 = -1e30f, lrow0 = 0.f, lrow1 = 0.f;

    for (int kt = 0; kt < S_LEN / KT; kt++) {
        __syncthreads();   // previous iteration's Ks/Vs reads done
        const float* kgt = kg + kt * KT * DKH;
        const float* vgt = vg + kt * KT * DKH;
        // K/V tiles 64x64 each: 512 thr * 2 passes * 4 = 4096 per tile.
#pragma unroll
        for (int p = 0; p < 2; p++) {
            int idx = t + p * 512;
            int r = idx >> 4, c = (idx & 15) * 4;
            float4 kv = *(const float4*)&kgt[r * DKH + c];
            Ks[r * KS_STR + c + 0] = f2tf32(kv.x);
            Ks[r * KS_STR + c + 1] = f2tf32(kv.y);
            Ks[r * KS_STR + c + 2] = f2tf32(kv.z);
            Ks[r * KS_STR + c + 3] = f2tf32(kv.w);
            float4 vv = *(const float4*)&vgt[r * DKH + c];
            Vs[r * VS_STR + c + 0] = f2tf32(vv.x);
            Vs[r * VS_STR + c + 1] = f2tf32(vv.y);
            Vs[r * VS_STR + c + 2] = f2tf32(vv.z);
            Vs[r * VS_STR + c + 3] = f2tf32(vv.w);
        }
        __syncthreads();

        // S = Q @ K^T  (warp: 16 rows x 64 cols)
        float s[8][4];
#pragma unroll
        for (int i = 0; i < 8; i++)
#pragma unroll
            for (int j = 0; j < 4; j++) s[i][j] = 0.f;

#pragma unroll
        for (int kk = 0; kk < 64; kk += 8) {
            uint32_t a[4];
            a[0] = __float_as_uint(Qs[rA * QS_STR + kk + tig]);
            a[1] = __float_as_uint(Qs[(rA + 8) * QS_STR + kk + tig]);
            a[2] = __float_as_uint(Qs[rA * QS_STR + kk + 4 + tig]);
            a[3] = __float_as_uint(Qs[(rA + 8) * QS_STR + kk + 4 + tig]);
#pragma unroll
            for (int nt = 0; nt < 8; nt++) {
                uint32_t b[2];
                b[0] = __float_as_uint(Ks[(nt * 8 + gid) * KS_STR + kk + tig]);
                b[1] = __float_as_uint(Ks[(nt * 8 + gid) * KS_STR + kk + 4 + tig]);
                mma_tf32(s[nt], a, b);
            }
        }

        // online softmax (rows rA and rA+8; reduce across tig via shfl)
        float mx0 = -1e30f, mx1 = -1e30f;
#pragma unroll
        for (int nt = 0; nt < 8; nt++) {
            s[nt][0] *= 0.125f; s[nt][1] *= 0.125f;
            s[nt][2] *= 0.125f; s[nt][3] *= 0.125f;
            mx0 = fmaxf(mx0, fmaxf(s[nt][0], s[nt][1]));
            mx1 = fmaxf(mx1, fmaxf(s[nt][2], s[nt][3]));
        }
        mx0 = fmaxf(mx0, __shfl_xor_sync(0xffffffffu, mx0, 1));
        mx0 = fmaxf(mx0, __shfl_xor_sync(0xffffffffu, mx0, 2));
        mx1 = fmaxf(mx1, __shfl_xor_sync(0xffffffffu, mx1, 1));
        mx1 = fmaxf(mx1, __shfl_xor_sync(0xffffffffu, mx1, 2));

        float nm0 = fmaxf(mrow0, mx0), nm1 = fmaxf(mrow1, mx1);
        float al0 = __expf(mrow0 - nm0), al1 = __expf(mrow1 - nm1);
        mrow0 = nm0; mrow1 = nm1;

        float sum0 = 0.f, sum1 = 0.f;
#pragma unroll
        for (int nt = 0; nt < 8; nt++) {
            float p0 = __expf(s[nt][0] - nm0), p1 = __expf(s[nt][1] - nm0);
            float p2 = __expf(s[nt][2] - nm1), p3 = __expf(s[nt][3] - nm1);
            sum0 += p0 + p1; sum1 += p2 + p3;
            int cc = nt * 8 + tig * 2;
            *(float2*)&Ps[rA * PS_STR + cc]       = make_float2(f2tf32(p0), f2tf32(p1));
            *(float2*)&Ps[(rA + 8) * PS_STR + cc] = make_float2(f2tf32(p2), f2tf32(p3));
        }
        sum0 += __shfl_xor_sync(0xffffffffu, sum0, 1);
        sum0 += __shfl_xor_sync(0xffffffffu, sum0, 2);
        sum1 += __shfl_xor_sync(0xffffffffu, sum1, 1);
        sum1 += __shfl_xor_sync(0xffffffffu, sum1, 2);
        lrow0 = lrow0 * al0 + sum0;
        lrow1 = lrow1 * al1 + sum1;
#pragma unroll
        for (int nt = 0; nt < 8; nt++) {
            o[nt][0] *= al0; o[nt][1] *= al0;
            o[nt][2] *= al1; o[nt][3] *= al1;
        }
        __syncwarp();   // Ps rows are warp-private; order write->read

        // O += P @ V  (warp: 16 rows x 64 cols, k over 64)
#pragma unroll
        for (int kk = 0; kk < 64; kk += 8) {
            uint32_t a[4];
            a[0] = __float_as_uint(Ps[rA * PS_STR + kk + tig]);
            a[1] = __float_as_uint(Ps[(rA + 8) * PS_STR + kk + tig]);
            a[2] = __float_as_uint(Ps[rA * PS_STR + kk + 4 + tig]);
            a[3] = __float_as_uint(Ps[(rA + 8) * PS_STR + kk + 4 + tig]);
#pragma unroll
            for (int nt = 0; nt < 8; nt++) {
                uint32_t b[2];
                b[0] = __float_as_uint(Vs[(kk + tig) * VS_STR + nt * 8 + gid]);
                b[1] = __float_as_uint(Vs[(kk + 4 + tig) * VS_STR + nt * 8 + gid]);
                mma_tf32(o[nt], a, b);
            }
        }
    }

    // epilogue: normalize, scatter to [B*S, D] with head offset
    float il0 = 1.f / lrow0, il1 = 1.f / lrow1;
    int bb = bh >> 4, hh = bh & 15;
    int q0 = qt * QT + rA;
    size_t base0 = ((size_t)(bb * S_LEN + q0)) * D_MODEL + hh * DKH;
    size_t base1 = base0 + (size_t)8 * D_MODEL;
#pragma unroll
    for (int nt = 0; nt < 8; nt++) {
        int dd = nt * 8 + tig * 2;
        *(float2*)&AO[base0 + dd] = make_float2(o[nt][0] * il0, o[nt][1] * il0);
        *(float2*)&AO[base1 + dd] = make_float2(o[nt][2] * il1, o[nt][3] * il1);
    }
}

// ============================================================================
extern "C" void kernel_launch(void* const* d_in, const int* in_sizes, int n_in,
                              void* d_out, int out_size) {
    (void)in_sizes; (void)n_in; (void)out_size;
    const float* x  = (const float*)d_in[0];
    const float* Wq = (const float*)d_in[1];
    const float* bq = (const float*)d_in[2];
    const float* Wk = (const float*)d_in[3];
    const float* bk = (const float*)d_in[4];
    const float* Wv = (const float*)d_in[5];
    const float* bv = (const float*)d_in[6];
    const float* Wo = (const float*)d_in[7];
    const float* bo = (const float*)d_in[8];
    float* out = (float*)d_out;

    float *pq, *pk, *pv, *pao;
    cudaGetSymbolAddress((void**)&pq,  g_q);
    cudaGetSymbolAddress((void**)&pk,  g_k);
    cudaGetSymbolAddress((void**)&pv,  g_v);
    cudaGetSymbolAddress((void**)&pao, g_ao);

    cudaFuncSetAttribute(attn_kernel,
                         cudaFuncAttributeMaxDynamicSharedMemorySize,
                         SM_TOT * (int)sizeof(float));

    dim3 gq(D_MODEL / 128, M_TOTAL / 128, 3);   // (8, 32, 3) fused QKV
    gemm_qkv_kernel<<<gq, 256>>>(x, Wq, bq, Wk, bk, Wv, bv, pq, pk, pv);
    attn_kernel<<<dim3(S_LEN / QT, BATCH * NH), 512, SM_TOT * sizeof(float)>>>(pq, pk, pv, pao);
    dim3 gg(D_MODEL / 128, M_TOTAL / 128);      // (8, 32)
    gemm_out_kernel<<<gg, 256>>>(pao, Wo, bo, out);
}